// round 2
// baseline (speedup 1.0000x reference)
#include <cuda_runtime.h>
#include <cstdint>

#define SEQ   2048
#define BATCH 128
#define INP   64
#define HID   256
#define GH    1024   // 4*HID
#define OUTD  64

typedef unsigned long long ull;

// packed 2xfp32 FMA (B300: FFMA-3reg is half-rate; f32x2 restores full rate)
#define FMA2(d, a, b) asm("fma.rn.f32x2 %0, %1, %2, %0;" : "+l"(d) : "l"(a), "l"(b))

__device__ __forceinline__ float hsum2(ull v) {
    float2 f = *(float2*)&v;
    return f.x + f.y;
}

// ---------------- scratch (static device arrays; no cudaMalloc) --------
__device__ float g_xw[(size_t)SEQ * BATCH * GH];   // x @ W_ih^T + b
__device__ float g_hs[(size_t)SEQ * BATCH * HID];  // h history

// =============================================================
// Kernel A: xw[m][g] = sum_i x[m][i]*W_ih[g][i] + b[g]
// M=262144, N=1024, K=64. Tile 64x128, 256 thr, thread 4x8, f32x2 over K.
// =============================================================
__global__ void __launch_bounds__(256) k_gemm_xw(const float* __restrict__ x,
                                                 const float* __restrict__ Wih,
                                                 const float* __restrict__ bias)
{
    extern __shared__ ulonglong2 smA[];
    ulonglong2* Xs = smA;            // 64 rows x 19 (16 used + pad)
    ulonglong2* Ws = smA + 64 * 19;  // 128 rows x 19

    const int t  = threadIdx.x;
    const int m0 = blockIdx.x * 64;
    const int n0 = blockIdx.y * 128;

    const ulonglong2* x4 = (const ulonglong2*)x;
    const ulonglong2* w4 = (const ulonglong2*)Wih;

    #pragma unroll
    for (int idx = t; idx < 64 * 16; idx += 256) {
        int r = idx >> 4, c = idx & 15;
        Xs[r * 19 + c] = x4[(size_t)(m0 + r) * 16 + c];
    }
    #pragma unroll
    for (int idx = t; idx < 128 * 16; idx += 256) {
        int r = idx >> 4, c = idx & 15;
        Ws[r * 19 + c] = w4[(size_t)(n0 + r) * 16 + c];
    }
    __syncthreads();

    const int tx = t & 15, ty = t >> 4;
    ull acc[4][8];
    #pragma unroll
    for (int i = 0; i < 4; i++)
        #pragma unroll
        for (int j = 0; j < 8; j++) acc[i][j] = 0ull;

    #pragma unroll
    for (int k4 = 0; k4 < 16; k4++) {
        ulonglong2 a2[4];
        #pragma unroll
        for (int i = 0; i < 4; i++) a2[i] = Xs[(ty + 16 * i) * 19 + k4];
        #pragma unroll
        for (int j = 0; j < 8; j++) {
            ulonglong2 b2 = Ws[(tx + 16 * j) * 19 + k4];
            #pragma unroll
            for (int i = 0; i < 4; i++) {
                FMA2(acc[i][j], a2[i].x, b2.x);
                FMA2(acc[i][j], a2[i].y, b2.y);
            }
        }
    }
    #pragma unroll
    for (int i = 0; i < 4; i++) {
        int m = m0 + ty + 16 * i;
        #pragma unroll
        for (int j = 0; j < 8; j++) {
            int n = n0 + tx + 16 * j;
            g_xw[(size_t)m * GH + n] = hsum2(acc[i][j]) + __ldg(&bias[n]);
        }
    }
}

// =============================================================
// Kernel B: persistent recurrent LSTM scan with clusters.
// 128 CTAs = 16 batch-groups(8 b) x 8 unit-groups(32 u => 128 gate rows).
// Cluster of 8 = the unit-groups of one batch-group; h exchanged via DSMEM.
// W_hh slice (130KB) resident in SMEM the whole scan. No global barrier.
// =============================================================
#define WSTRIDE 260   // floats per W row (pad)
#define HSTRIDE 268   // floats per H batch row (pad; breaks b<->b+4 conflicts)
#define LSTRIDE 132   // floats per L batch row

__global__ void __launch_bounds__(256, 1) __cluster_dims__(8, 1, 1)
k_lstm(const float* __restrict__ h0, const float* __restrict__ c0,
       const float* __restrict__ Whh)
{
    extern __shared__ float smR[];
    float* Wsm  = smR;                      // 128 x 260
    float* Hsm  = Wsm + 128 * WSTRIDE;      // 8 x 268  (full h, 256 used)
    float* Lsm  = Hsm + 8 * HSTRIDE;        // 8 x 132  (128 gate rows + pad)
    float* Csm  = Lsm + 8 * LSTRIDE;        // 8 x 32
    float* Hnew = Csm + 8 * 32;             // 8 x 32 (my slice, peers read it)

    const int t      = threadIdx.x;
    const int bgrp   = blockIdx.x >> 3;     // 0..15
    const int myrank = blockIdx.x & 7;      // == cluster rank
    const int b0g    = bgrp << 3;           // global batch base (8 batches)
    const int u0     = myrank << 5;         // global unit base (32 units)

    // --- load W_hh slice once: local row r = gate*32+u -> grow = gate*256+u0+u
    for (int idx = t; idx < 128 * 64; idx += 256) {
        int r = idx >> 6, c4 = idx & 63;
        int grow = ((r >> 5) << 8) + u0 + (r & 31);
        *(float4*)(Wsm + r * WSTRIDE + (c4 << 2)) =
            ((const float4*)Whh)[(size_t)grow * 64 + c4];
    }
    // --- init Hsm (full h for my 8 batches), Csm (my unit slice)
    for (int idx = t; idx < 8 * 64; idx += 256) {
        int b = idx >> 6, c4 = idx & 63;
        *(float4*)(Hsm + b * HSTRIDE + (c4 << 2)) =
            ((const float4*)h0)[(size_t)(b0g + b) * 64 + c4];
    }
    {
        int b = t >> 5, u = t & 31;
        Csm[(b << 5) + u] = c0[(size_t)(b0g + b) * HID + u0 + u];
    }
    __syncthreads();

    // GEMV mapping: warp w owns 16 gate rows; lane = 2*r_local + bg,
    // bg selects 4 batches (0-3 or 4-7).
    const int w    = t >> 5, lane = t & 31;
    const int r    = (w << 4) + (lane >> 1);     // local gate row 0..127
    const int bb   = (lane & 1) << 2;            // batch base 0 or 4
    const int grow = ((r >> 5) << 8) + u0 + (r & 31);

    const ulonglong2* Wr  = (const ulonglong2*)(Wsm + r * WSTRIDE);
    const ulonglong2* H0p = (const ulonglong2*)(Hsm + (bb + 0) * HSTRIDE);
    const ulonglong2* H1p = (const ulonglong2*)(Hsm + (bb + 1) * HSTRIDE);
    const ulonglong2* H2p = (const ulonglong2*)(Hsm + (bb + 2) * HSTRIDE);
    const ulonglong2* H3p = (const ulonglong2*)(Hsm + (bb + 3) * HSTRIDE);

    const uint32_t hnew_addr = (uint32_t)__cvta_generic_to_shared(Hnew);

    for (int step = 0; step < SEQ; step++) {
        // prefetch xw (DRAM; hidden under the ~2K-cycle GEMV)
        const float* xwp = g_xw + ((size_t)step * BATCH + b0g + bb) * GH + grow;
        float xv0 = xwp[0];
        float xv1 = xwp[GH];
        float xv2 = xwp[2 * GH];
        float xv3 = xwp[3 * GH];

        ull a0l = 0, a0h = 0, a1l = 0, a1h = 0, a2l = 0, a2h = 0, a3l = 0, a3h = 0;
        #pragma unroll 16
        for (int k4 = 0; k4 < 64; k4++) {
            ulonglong2 wv = Wr[k4];
            ulonglong2 h0v = H0p[k4];
            FMA2(a0l, wv.x, h0v.x); FMA2(a0h, wv.y, h0v.y);
            ulonglong2 h1v = H1p[k4];
            FMA2(a1l, wv.x, h1v.x); FMA2(a1h, wv.y, h1v.y);
            ulonglong2 h2v = H2p[k4];
            FMA2(a2l, wv.x, h2v.x); FMA2(a2h, wv.y, h2v.y);
            ulonglong2 h3v = H3p[k4];
            FMA2(a3l, wv.x, h3v.x); FMA2(a3h, wv.y, h3v.y);
        }
        Lsm[(bb + 0) * LSTRIDE + r] = hsum2(a0l) + hsum2(a0h) + xv0;
        Lsm[(bb + 1) * LSTRIDE + r] = hsum2(a1l) + hsum2(a1h) + xv1;
        Lsm[(bb + 2) * LSTRIDE + r] = hsum2(a2l) + hsum2(a2h) + xv2;
        Lsm[(bb + 3) * LSTRIDE + r] = hsum2(a3l) + hsum2(a3h) + xv3;
        __syncthreads();

        // gate update: warp per batch, lane per unit
        {
            int b = t >> 5, u = t & 31;
            const float* Lb = Lsm + b * LSTRIDE;
            float iv = Lb[u];
            float fv = Lb[32 + u];
            float gv = Lb[64 + u];
            float ov = Lb[96 + u];
            float ig = 1.f / (1.f + __expf(-iv));
            float fg = 1.f / (1.f + __expf(-fv));
            float gg = tanhf(gv);
            float og = 1.f / (1.f + __expf(-ov));
            float cc = fg * Csm[(b << 5) + u] + ig * gg;
            Csm[(b << 5) + u] = cc;
            float hh = og * tanhf(cc);
            Hnew[(b << 5) + u] = hh;
            Hsm[b * HSTRIDE + u0 + u] = hh;             // own column of Hsm
            g_hs[((size_t)step * BATCH + b0g + b) * HID + u0 + u] = hh;
        }

        // cluster barrier #1: all slices published in Hnew
        asm volatile("barrier.cluster.arrive.aligned;" ::: "memory");
        asm volatile("barrier.cluster.wait.aligned;"   ::: "memory");

        // pull 7 peers' slices via DSMEM into my Hsm
        if (step < SEQ - 1) {
            for (int item = t; item < 448; item += 256) {
                int p   = item >> 6;          // 0..6
                int rem = item & 63;
                int b   = rem >> 3, c4 = rem & 7;
                int peer = p + (p >= myrank ? 1 : 0);
                uint32_t laddr = hnew_addr + (((b << 5) + (c4 << 2)) << 2);
                uint32_t raddr;
                asm("mapa.shared::cluster.u32 %0, %1, %2;"
                    : "=r"(raddr) : "r"(laddr), "r"(peer));
                float vx, vy, vz, vw;
                asm volatile("ld.shared::cluster.v4.f32 {%0,%1,%2,%3}, [%4];"
                             : "=f"(vx), "=f"(vy), "=f"(vz), "=f"(vw)
                             : "r"(raddr));
                *(float4*)(Hsm + b * HSTRIDE + (peer << 5) + (c4 << 2)) =
                    make_float4(vx, vy, vz, vw);
            }
        }

        // cluster barrier #2: copies done before anyone overwrites Hnew
        asm volatile("barrier.cluster.arrive.aligned;" ::: "memory");
        asm volatile("barrier.cluster.wait.aligned;"   ::: "memory");
    }
}

// =============================================================
// Kernel C: out[m][o] = sum_h hs[m][h]*W_out[o][h] + b_out[o]
// M=262144, N=64, K=256. Tile 64x64, thread 4x4, f32x2 over K.
// =============================================================
__global__ void __launch_bounds__(256) k_gemm_out(const float* __restrict__ Wout,
                                                  const float* __restrict__ bout,
                                                  float* __restrict__ out)
{
    extern __shared__ ulonglong2 smC[];
    ulonglong2* Hs = smC;            // 64 x 19
    ulonglong2* Ws = smC + 64 * 19;  // 64 x 19

    const int t  = threadIdx.x;
    const int m0 = blockIdx.x * 64;
    const int tx = t & 15, ty = t >> 4;

    ull acc[4][4];
    #pragma unroll
    for (int i = 0; i < 4; i++)
        #pragma unroll
        for (int j = 0; j < 4; j++) acc[i][j] = 0ull;

    const ulonglong2* hs4 = (const ulonglong2*)g_hs;
    const ulonglong2* wo4 = (const ulonglong2*)Wout;

    for (int kc = 0; kc < 4; kc++) {
        __syncthreads();
        #pragma unroll
        for (int idx = t; idx < 64 * 16; idx += 256) {
            int r = idx >> 4, c = idx & 15;
            Hs[r * 19 + c] = hs4[(size_t)(m0 + r) * 64 + kc * 16 + c];
            Ws[r * 19 + c] = wo4[(size_t)r * 64 + kc * 16 + c];
        }
        __syncthreads();
        #pragma unroll
        for (int k4 = 0; k4 < 16; k4++) {
            ulonglong2 a2[4];
            #pragma unroll
            for (int i = 0; i < 4; i++) a2[i] = Hs[(ty + 16 * i) * 19 + k4];
            #pragma unroll
            for (int j = 0; j < 4; j++) {
                ulonglong2 b2 = Ws[(tx + 16 * j) * 19 + k4];
                #pragma unroll
                for (int i = 0; i < 4; i++) {
                    FMA2(acc[i][j], a2[i].x, b2.x);
                    FMA2(acc[i][j], a2[i].y, b2.y);
                }
            }
        }
    }
    #pragma unroll
    for (int i = 0; i < 4; i++) {
        size_t m = (size_t)(m0 + ty + 16 * i);
        #pragma unroll
        for (int j = 0; j < 4; j++) {
            int n = tx + 16 * j;
            out[m * OUTD + n] = hsum2(acc[i][j]) + __ldg(&bout[n]);
        }
    }
}

// =============================================================
extern "C" void kernel_launch(void* const* d_in, const int* in_sizes, int n_in,
                              void* d_out, int out_size)
{
    (void)in_sizes; (void)n_in; (void)out_size;
    const float* x    = (const float*)d_in[0];
    const float* h0   = (const float*)d_in[1];
    const float* c0   = (const float*)d_in[2];
    const float* Wih  = (const float*)d_in[3];
    const float* Whh  = (const float*)d_in[4];
    const float* b    = (const float*)d_in[5];
    const float* Wout = (const float*)d_in[6];
    const float* bout = (const float*)d_in[7];
    float* out = (float*)d_out;

    const int smA = (64 + 128) * 19 * 16;                                   // 58368 B
    const int smR = (128 * WSTRIDE + 8 * HSTRIDE + 8 * LSTRIDE + 8 * 32 + 8 * 32) * 4; // 147968 B
    const int smC = (64 + 64) * 19 * 16;                                    // 38912 B

    cudaFuncSetAttribute(k_gemm_xw,  cudaFuncAttributeMaxDynamicSharedMemorySize, smA);
    cudaFuncSetAttribute(k_lstm,     cudaFuncAttributeMaxDynamicSharedMemorySize, smR);
    cudaFuncSetAttribute(k_gemm_out, cudaFuncAttributeMaxDynamicSharedMemorySize, smC);

    dim3 gridA((SEQ * BATCH) / 64, GH / 128);
    k_gemm_xw<<<gridA, 256, smA>>>(x, Wih, b);

    k_lstm<<<128, 256, smR>>>(h0, c0, Whh);

    k_gemm_out<<<(SEQ * BATCH) / 64, 256, smC>>>(Wout, bout, out);
}